// round 2
// baseline (speedup 1.0000x reference)
#include <cuda_runtime.h>

#define CONCEPTS 128
#define MM 14          // nb_mod_max + 2
#define DC 128         // concept dim
#define DIN 3
#define BMAX 131072
#define ROWS_PER_WARP 16

// __device__ global scratch (no allocations allowed anywhere).
__device__ float g_G[CONCEPTS * 8];        // padded Gram per concept
__device__ int   g_cnt[CONCEPTS];          // histogram
__device__ int   g_off[CONCEPTS * 32];     // working offsets, 128B-padded
__device__ int   g_perm[BMAX];             // rows sorted by concept

// ---------------------------------------------------------------------------
// G[c] = W[c] W[c]^T  (3x3 symmetric, 6 uniques). One warp per concept.
// ---------------------------------------------------------------------------
__global__ void gmat_kernel(const float* __restrict__ W) {
    int c = blockIdx.x;
    int lane = threadIdx.x;
    const float4* w = reinterpret_cast<const float4*>(W + (size_t)c * DIN * DC);
    float4 a = w[lane];
    float4 b = w[32 + lane];
    float4 d = w[64 + lane];
    float s[6];
    s[0] = a.x*a.x + a.y*a.y + a.z*a.z + a.w*a.w;
    s[1] = a.x*b.x + a.y*b.y + a.z*b.z + a.w*b.w;
    s[2] = a.x*d.x + a.y*d.y + a.z*d.z + a.w*d.w;
    s[3] = b.x*b.x + b.y*b.y + b.z*b.z + b.w*b.w;
    s[4] = b.x*d.x + b.y*d.y + b.z*d.z + b.w*d.w;
    s[5] = d.x*d.x + d.y*d.y + d.z*d.z + d.w*d.w;
    #pragma unroll
    for (int off = 16; off; off >>= 1)
        #pragma unroll
        for (int k = 0; k < 6; k++)
            s[k] += __shfl_xor_sync(0xffffffffu, s[k], off);
    if (lane == 0) {
        #pragma unroll
        for (int k = 0; k < 6; k++) g_G[c * 8 + k] = s[k];
    }
}

// ---------------------------------------------------------------------------
// Counting sort by concept (128 buckets)
// ---------------------------------------------------------------------------
__global__ void zero_kernel() {
    g_cnt[threadIdx.x] = 0;
}

__global__ void hist_kernel(const int* __restrict__ concept_ids, int nrows) {
    __shared__ int h[CONCEPTS];
    int t = threadIdx.x;
    if (t < CONCEPTS) h[t] = 0;
    __syncthreads();
    for (int i = blockIdx.x * blockDim.x + t; i < nrows; i += gridDim.x * blockDim.x)
        atomicAdd(&h[concept_ids[i]], 1);
    __syncthreads();
    if (t < CONCEPTS && h[t]) atomicAdd(&g_cnt[t], h[t]);
}

__global__ void scan_kernel() {
    // 128 threads, naive exclusive prefix (tiny)
    __shared__ int c[CONCEPTS];
    int t = threadIdx.x;
    c[t] = g_cnt[t];
    __syncthreads();
    int s = 0;
    for (int k = 0; k < t; k++) s += c[k];
    g_off[t * 32] = s;
}

__global__ void scatter_kernel(const int* __restrict__ concept_ids, int nrows) {
    int i = blockIdx.x * blockDim.x + threadIdx.x;
    if (i >= nrows) return;
    int c = concept_ids[i];
    int pos = atomicAdd(&g_off[c * 32], 1);
    g_perm[pos] = i;
}

// ---------------------------------------------------------------------------
// Main: one warp per 16 sorted rows. W[c] cached in registers across rows
// sharing a concept (common case after sort).
//   v = W^T u (butterfly); score_m = e^T G e - 2 e.v + mask; argmin -> resp
// ---------------------------------------------------------------------------
__global__ void impact_kernel(
    const int*   __restrict__ user_ids,
    const int*   __restrict__ item_ids,
    const int*   __restrict__ concept_ids,
    const float* __restrict__ uemb,
    const float* __restrict__ irw,
    const float* __restrict__ W,
    const float* __restrict__ maskt,
    const int*   __restrict__ nbmod,
    float*       __restrict__ out,
    int nrows)
{
    const unsigned FULL = 0xffffffffu;
    int warp = (int)((blockIdx.x * blockDim.x + threadIdx.x) >> 5);
    int lane = threadIdx.x & 31;
    long base = (long)warp * ROWS_PER_WARP;
    if (base >= nrows) return;
    int cnt = nrows - base < ROWS_PER_WARP ? (int)(nrows - base) : ROWS_PER_WARP;

    // Gather the 16 rows' metadata once (lanes 0..cnt-1)
    int r = 0, uid = 0, it = 0, cc = 0;
    if (lane < cnt) {
        r   = g_perm[base + lane];
        uid = user_ids[r];
        it  = item_ids[r];
        cc  = concept_ids[r];
    }

    int ccur = -1;
    float4 w0, w1, w2;
    float G0 = 0, G1 = 0, G2 = 0, G3 = 0, G4 = 0, G5 = 0;

    for (int j = 0; j < cnt; j++) {
        int rj = __shfl_sync(FULL, r,   j);
        int uj = __shfl_sync(FULL, uid, j);
        int ij = __shfl_sync(FULL, it,  j);
        int cj = __shfl_sync(FULL, cc,  j);

        if (cj != ccur) {   // warp-uniform branch
            ccur = cj;
            const float4* wv = reinterpret_cast<const float4*>(W + (size_t)cj * DIN * DC);
            w0 = wv[lane];
            w1 = wv[32 + lane];
            w2 = wv[64 + lane];
            const float* G = g_G + cj * 8;
            G0 = __ldg(G + 0); G1 = __ldg(G + 1); G2 = __ldg(G + 2);
            G3 = __ldg(G + 3); G4 = __ldg(G + 4); G5 = __ldg(G + 5);
        }

        float4 uu = *reinterpret_cast<const float4*>(uemb + (size_t)uj * DC + lane * 4);
        float v0 = uu.x*w0.x + uu.y*w0.y + uu.z*w0.z + uu.w*w0.w;
        float v1 = uu.x*w1.x + uu.y*w1.y + uu.z*w1.z + uu.w*w1.w;
        float v2 = uu.x*w2.x + uu.y*w2.y + uu.z*w2.z + uu.w*w2.w;
        #pragma unroll
        for (int off = 16; off; off >>= 1) {
            v0 += __shfl_xor_sync(FULL, v0, off);
            v1 += __shfl_xor_sync(FULL, v1, off);
            v2 += __shfl_xor_sync(FULL, v2, off);
        }

        float score = __int_as_float(0x7f800000);   // +inf
        if (lane < MM) {
            const float* e = irw + ((size_t)ij * MM + lane) * DIN;
            float e0 = e[0], e1 = e[1], e2 = e[2];
            float q = e0*e0*G0 + e1*e1*G3 + e2*e2*G5
                    + 2.0f*(e0*e1*G1 + e0*e2*G2 + e1*e2*G4);
            score = q - 2.0f*(e0*v0 + e1*v1 + e2*v2)
                  + maskt[(size_t)ij * MM + lane];
        }

        // argmin over lanes 0..15 (14,15 hold +inf); closed under offsets <16
        int bi = lane;
        #pragma unroll
        for (int off = 8; off; off >>= 1) {
            float ov = __shfl_xor_sync(FULL, score, off);
            int   oi = __shfl_xor_sync(FULL, bi,    off);
            if (ov < score || (ov == score && oi < bi)) { score = ov; bi = oi; }
        }

        if (lane == 0) {
            float nb = (float)nbmod[ij];
            out[rj] = ((float)bi - 1.0f) / (nb - 1.0f) + 1.0f;
        }
    }
}

extern "C" void kernel_launch(void* const* d_in, const int* in_sizes, int n_in,
                              void* d_out, int out_size) {
    const int*   user_ids    = (const int*)  d_in[0];
    const int*   item_ids    = (const int*)  d_in[1];
    const int*   concept_ids = (const int*)  d_in[2];
    const float* uemb        = (const float*)d_in[3];
    const float* irw         = (const float*)d_in[4];
    const float* W           = (const float*)d_in[5];
    const float* maskt       = (const float*)d_in[6];
    const int*   nbmod       = (const int*)  d_in[7];
    float* out = (float*)d_out;
    int nrows = in_sizes[0];

    gmat_kernel<<<CONCEPTS, 32>>>(W);
    zero_kernel<<<1, CONCEPTS>>>();
    hist_kernel<<<148, 256>>>(concept_ids, nrows);
    scan_kernel<<<1, CONCEPTS>>>();
    scatter_kernel<<<(nrows + 255) / 256, 256>>>(concept_ids, nrows);

    int warps = (nrows + ROWS_PER_WARP - 1) / ROWS_PER_WARP;
    int blocks = (warps + 7) / 8;   // 256 threads = 8 warps
    impact_kernel<<<blocks, 256>>>(
        user_ids, item_ids, concept_ids, uemb, irw, W, maskt, nbmod, out, nrows);
}

// round 3
// speedup vs baseline: 1.7758x; 1.7758x over previous
#include <cuda_runtime.h>

#define CONCEPTS 128
#define MM 14          // nb_mod_max + 2
#define DC 128         // concept dim
#define DIN 3

// Per-concept Gram G = W[c] W[c]^T, padded to 8 floats: {G00,G01,G02,G11,G12,G22,_,_}
__device__ float g_G[CONCEPTS * 8];

// ---------------------------------------------------------------------------
// G[c] = W[c] W[c]^T. One warp per concept.
// ---------------------------------------------------------------------------
__global__ void gmat_kernel(const float* __restrict__ W) {
    int c = blockIdx.x;
    int lane = threadIdx.x;
    const float4* w = reinterpret_cast<const float4*>(W + (size_t)c * DIN * DC);
    float4 a = w[lane];
    float4 b = w[32 + lane];
    float4 d = w[64 + lane];
    float s[6];
    s[0] = a.x*a.x + a.y*a.y + a.z*a.z + a.w*a.w;
    s[1] = a.x*b.x + a.y*b.y + a.z*b.z + a.w*b.w;
    s[2] = a.x*d.x + a.y*d.y + a.z*d.z + a.w*d.w;
    s[3] = b.x*b.x + b.y*b.y + b.z*b.z + b.w*b.w;
    s[4] = b.x*d.x + b.y*d.y + b.z*d.z + b.w*d.w;
    s[5] = d.x*d.x + d.y*d.y + d.z*d.z + d.w*d.w;
    #pragma unroll
    for (int off = 16; off; off >>= 1)
        #pragma unroll
        for (int k = 0; k < 6; k++)
            s[k] += __shfl_xor_sync(0xffffffffu, s[k], off);
    if (lane == 0) {
        #pragma unroll
        for (int k = 0; k < 6; k++) g_G[c * 8 + k] = s[k];
        g_G[c * 8 + 6] = 0.0f;
        g_G[c * 8 + 7] = 0.0f;
    }
}

// ---------------------------------------------------------------------------
// Main: 2 rows per warp, 16 lanes per row (parallel halves).
//   lane = 16*half + hl; row = 2*warp + half.
//   Channel split: lane hl owns channels [4hl,4hl+4) and [64+4hl, 64+4hl+4)
//   so each LDG.128 is contiguous 256B per half (2 lines) — fully coalesced.
//   v = W[c] u via 4-stage butterfly within each 16-lane half.
//   score_m = e^T G e - 2 e.v + mask ; 4-stage argmin ; response.
// ---------------------------------------------------------------------------
__global__ void __launch_bounds__(256) impact_kernel(
    const int*   __restrict__ user_ids,
    const int*   __restrict__ item_ids,
    const int*   __restrict__ concept_ids,
    const float* __restrict__ uemb,     // (USER_N, 128)
    const float* __restrict__ irw,      // (ITEM_N*14, 3)
    const float* __restrict__ W,        // (128, 3, 128)
    const float* __restrict__ maskt,    // (ITEM_N, 14)
    const int*   __restrict__ nbmod,    // (ITEM_N,)
    float*       __restrict__ out,
    int nrows)
{
    const unsigned FULL = 0xffffffffu;
    int warp = (int)((blockIdx.x * blockDim.x + threadIdx.x) >> 5);
    int lane = threadIdx.x & 31;
    int half = lane >> 4;
    int hl   = lane & 15;

    long row = (long)warp * 2 + half;
    bool active = row < nrows;
    long ridx = active ? row : 0;       // clamp: row 0 always exists (nrows>0)

    int uid = user_ids[ridx];
    int it  = item_ids[ridx];
    int cc  = concept_ids[ridx];

    // ---- gather u and W[c] (coalesced float4, 2 lines per half per LDG) ----
    const float* ub = uemb + (size_t)uid * DC;
    float4 ua = *reinterpret_cast<const float4*>(ub + 4 * hl);
    float4 uc = *reinterpret_cast<const float4*>(ub + 64 + 4 * hl);

    const float* wb = W + (size_t)cc * DIN * DC;
    float4 w0a = *reinterpret_cast<const float4*>(wb + 4 * hl);
    float4 w0b = *reinterpret_cast<const float4*>(wb + 64 + 4 * hl);
    float4 w1a = *reinterpret_cast<const float4*>(wb + DC + 4 * hl);
    float4 w1b = *reinterpret_cast<const float4*>(wb + DC + 64 + 4 * hl);
    float4 w2a = *reinterpret_cast<const float4*>(wb + 2 * DC + 4 * hl);
    float4 w2b = *reinterpret_cast<const float4*>(wb + 2 * DC + 64 + 4 * hl);

    float v0 = ua.x*w0a.x + ua.y*w0a.y + ua.z*w0a.z + ua.w*w0a.w
             + uc.x*w0b.x + uc.y*w0b.y + uc.z*w0b.z + uc.w*w0b.w;
    float v1 = ua.x*w1a.x + ua.y*w1a.y + ua.z*w1a.z + ua.w*w1a.w
             + uc.x*w1b.x + uc.y*w1b.y + uc.z*w1b.z + uc.w*w1b.w;
    float v2 = ua.x*w2a.x + ua.y*w2a.y + ua.z*w2a.z + ua.w*w2a.w
             + uc.x*w2b.x + uc.y*w2b.y + uc.z*w2b.z + uc.w*w2b.w;

    // 4-stage butterfly all-reduce within each 16-lane half (offsets < 16)
    #pragma unroll
    for (int off = 8; off; off >>= 1) {
        v0 += __shfl_xor_sync(FULL, v0, off);
        v1 += __shfl_xor_sync(FULL, v1, off);
        v2 += __shfl_xor_sync(FULL, v2, off);
    }

    // ---- per-modality score (lanes hl=0..13 of each half) ----
    const float4* Gp = reinterpret_cast<const float4*>(g_G + cc * 8);
    float4 Ga = __ldg(Gp);        // G00 G01 G02 G11
    float4 Gb = __ldg(Gp + 1);    // G12 G22 _ _

    float score = __int_as_float(0x7f800000);   // +inf for hl>=14
    if (hl < MM) {
        const float* e = irw + ((size_t)it * MM + hl) * DIN;
        float e0 = e[0], e1 = e[1], e2 = e[2];
        float q = e0*e0*Ga.x + e1*e1*Ga.w + e2*e2*Gb.y
                + 2.0f*(e0*e1*Ga.y + e0*e2*Ga.z + e1*e2*Gb.x);
        score = q - 2.0f*(e0*v0 + e1*v1 + e2*v2)
              + maskt[(size_t)it * MM + hl];
    }

    // lexicographic argmin within each 16-lane half
    int bi = hl;
    #pragma unroll
    for (int off = 8; off; off >>= 1) {
        float ov = __shfl_xor_sync(FULL, score, off);
        int   oi = __shfl_xor_sync(FULL, bi,    off);
        if (ov < score || (ov == score && oi < bi)) { score = ov; bi = oi; }
    }

    if (hl == 0 && active) {
        float nb = (float)nbmod[it];
        out[row] = ((float)bi - 1.0f) / (nb - 1.0f) + 1.0f;
    }
}

extern "C" void kernel_launch(void* const* d_in, const int* in_sizes, int n_in,
                              void* d_out, int out_size) {
    const int*   user_ids    = (const int*)  d_in[0];
    const int*   item_ids    = (const int*)  d_in[1];
    const int*   concept_ids = (const int*)  d_in[2];
    const float* uemb        = (const float*)d_in[3];
    const float* irw         = (const float*)d_in[4];
    const float* W           = (const float*)d_in[5];
    const float* maskt       = (const float*)d_in[6];
    const int*   nbmod       = (const int*)  d_in[7];
    float* out = (float*)d_out;
    int nrows = in_sizes[0];

    gmat_kernel<<<CONCEPTS, 32>>>(W);

    int warps = (nrows + 1) / 2;          // 2 rows per warp
    int blocks = (warps + 7) / 8;         // 8 warps (256 threads) per block
    impact_kernel<<<blocks, 256>>>(
        user_ids, item_ids, concept_ids, uemb, irw, W, maskt, nbmod, out, nrows);
}